// round 2
// baseline (speedup 1.0000x reference)
#include <cuda_runtime.h>
#include <math.h>

#define N_SRC   40000
#define L_TGT   4096
#define NSPLIT  20
#define CHUNK   (N_SRC / NSPLIT)   /* 2000 */
#define TILE    200
#define NT      128
/* 1/(sigma*ln2), sigma=2.5 : exp(-d/sigma) = 2^(-d*K) = ex2(-sqrt(K^2 d^2)) */
#define KSCALE  0.5770780163555852f
#define EPSC    0.01f

/* ---------------- scratch (no allocations allowed) ---------------- */
/* g*: raw coords + ((x^2+y^2)+z^2)  (reference-rounding norm)       */
/* s*: K-scaled coords *(-2) + |Kp|^2 (fast RBF form)                */
__device__ float4 d_g1[N_SRC], d_g2[N_SRC], d_s1[N_SRC], d_s2[N_SRC];
__device__ float  d_pbestL[NSPLIT * L_TGT], d_pbestR[NSPLIT * L_TGT];
__device__ int    d_pidxL [NSPLIT * L_TGT], d_pidxR [NSPLIT * L_TGT];
__device__ float  d_pnL   [NSPLIT * L_TGT], d_pnR   [NSPLIT * L_TGT];
__device__ float  d_paccL [NSPLIT * 12 * L_TGT], d_paccR[NSPLIT * 12 * L_TGT];

__device__ __forceinline__ float sqrt_ap(float x) {
    float r; asm("sqrt.approx.f32 %0, %1;" : "=f"(r) : "f"(x)); return r;
}
__device__ __forceinline__ float ex2_ap(float x) {
    float r; asm("ex2.approx.f32 %0, %1;" : "=f"(r) : "f"(x)); return r;
}
/* reference-matching squared norm: ((x*x + y*y) + z*z), no FMA contraction */
__device__ __forceinline__ float norm2_ref(float x, float y, float z) {
    return __fadd_rn(__fadd_rn(__fmul_rn(x, x), __fmul_rn(y, y)), __fmul_rn(z, z));
}
/* reference-matching d2: (sa+sb) - 2*dot, dot = fma chain k ascending from 0 */
__device__ __forceinline__ float d2_ref(float ax, float ay, float az, float sa,
                                        float bx, float by, float bz, float sb) {
    float dot = fmaf(az, bz, fmaf(ay, by, __fmul_rn(ax, bx)));
    return __fsub_rn(__fadd_rn(sa, sb), __fmul_rn(2.0f, dot));
}

/* ------------- prep ------------- */
__global__ void prep_kernel(const float* __restrict__ g1, const float* __restrict__ g2,
                            const float* __restrict__ s1, const float* __restrict__ s2) {
    int i = blockIdx.x * blockDim.x + threadIdx.x;
    if (i >= N_SRC) return;
    float x, y, z;
    x = g1[3*i]; y = g1[3*i+1]; z = g1[3*i+2];
    d_g1[i] = make_float4(x, y, z, norm2_ref(x, y, z));
    x = g2[3*i]; y = g2[3*i+1]; z = g2[3*i+2];
    d_g2[i] = make_float4(x, y, z, norm2_ref(x, y, z));
    x = KSCALE * s1[3*i]; y = KSCALE * s1[3*i+1]; z = KSCALE * s1[3*i+2];
    d_s1[i] = make_float4(-2.f*x, -2.f*y, -2.f*z, x*x + y*y + z*z);
    x = KSCALE * s2[3*i]; y = KSCALE * s2[3*i+1]; z = KSCALE * s2[3*i+2];
    d_s2[i] = make_float4(-2.f*x, -2.f*y, -2.f*z, x*x + y*y + z*z);
}

/* ------------- pass1: argmin + rbf partial sums over an N-chunk ------------- */
__global__ void __launch_bounds__(NT, 5)
pass1_kernel(const float* __restrict__ locs_left, const float* __restrict__ locs_right,
             const float* __restrict__ s1_x, const float* __restrict__ s2_x) {
    __shared__ float4 shg1[TILE], shg2[TILE], shs1[TILE], shs2[TILE];
    __shared__ float4 shf1[TILE * 3], shf2[TILE * 3];

    const int l     = blockIdx.x * NT + threadIdx.x;   /* target row */
    const int split = blockIdx.y;
    const int base  = split * CHUNK;

    /* target constants */
    float tlx = locs_left[3*l], tly = locs_left[3*l+1], tlz = locs_left[3*l+2];
    float trx = locs_right[3*l], tryy = locs_right[3*l+1], trz = locs_right[3*l+2];
    float saL = norm2_ref(tlx, tly, tlz);
    float saR = norm2_ref(trx, tryy, trz);
    float qlx = KSCALE*tlx, qly = KSCALE*tly, qlz = KSCALE*tlz;
    float qrx = KSCALE*trx, qry = KSCALE*tryy, qrz = KSCALE*trz;
    float qln2 = qlx*qlx + qly*qly + qlz*qlz;
    float qrn2 = qrx*qrx + qry*qry + qrz*qrz;

    float bestL = 3.4e38f, bestR = 3.4e38f;
    int   bidxL = 0, bidxR = 0;
    float nL = 0.f, nR = 0.f;
    float aL[12], aR[12];
#pragma unroll
    for (int k = 0; k < 12; k++) { aL[k] = 0.f; aR[k] = 0.f; }

    const float4* f1g = (const float4*)s1_x;
    const float4* f2g = (const float4*)s2_x;

    for (int t = 0; t < CHUNK; t += TILE) {
        __syncthreads();
        for (int i = threadIdx.x; i < TILE; i += NT) {
            int j = base + t + i;
            shg1[i] = d_g1[j]; shg2[i] = d_g2[j];
            shs1[i] = d_s1[j]; shs2[i] = d_s2[j];
        }
        for (int i = threadIdx.x; i < TILE * 3; i += NT) {
            int j = (base + t) * 3 + i;
            shf1[i] = f1g[j]; shf2[i] = f2g[j];
        }
        __syncthreads();

#pragma unroll 2
        for (int j = 0; j < TILE; j++) {
            int src = base + t + j;
            /* argmin with reference-matching rounding */
            float4 g1 = shg1[j];
            float d2 = d2_ref(tlx, tly, tlz, saL, g1.x, g1.y, g1.z, g1.w);
            if (d2 < bestL) { bestL = d2; bidxL = src; }
            float4 g2 = shg2[j];
            float e2 = d2_ref(trx, tryy, trz, saR, g2.x, g2.y, g2.z, g2.w);
            if (e2 < bestR) { bestR = e2; bidxR = src; }

            /* rbf (K-scaled coords, -2 folded): w = 2^(-sqrt(d2k)) */
            float4 s1 = shs1[j];
            float r2 = fmaf(qlx, s1.x, fmaf(qly, s1.y, fmaf(qlz, s1.z, qln2 + s1.w)));
            r2 = fmaxf(r2, 0.f);
            float w1 = ex2_ap(-sqrt_ap(r2));
            nL += w1;
            float4 s2 = shs2[j];
            float u2 = fmaf(qrx, s2.x, fmaf(qry, s2.y, fmaf(qrz, s2.z, qrn2 + s2.w)));
            u2 = fmaxf(u2, 0.f);
            float w2 = ex2_ap(-sqrt_ap(u2));
            nR += w2;

            float4 f;
            f = shf1[3*j+0];
            aL[0] = fmaf(w1, f.x, aL[0]); aL[1] = fmaf(w1, f.y, aL[1]);
            aL[2] = fmaf(w1, f.z, aL[2]); aL[3] = fmaf(w1, f.w, aL[3]);
            f = shf1[3*j+1];
            aL[4] = fmaf(w1, f.x, aL[4]); aL[5] = fmaf(w1, f.y, aL[5]);
            aL[6] = fmaf(w1, f.z, aL[6]); aL[7] = fmaf(w1, f.w, aL[7]);
            f = shf1[3*j+2];
            aL[8] = fmaf(w1, f.x, aL[8]); aL[9] = fmaf(w1, f.y, aL[9]);
            aL[10] = fmaf(w1, f.z, aL[10]); aL[11] = fmaf(w1, f.w, aL[11]);
            f = shf2[3*j+0];
            aR[0] = fmaf(w2, f.x, aR[0]); aR[1] = fmaf(w2, f.y, aR[1]);
            aR[2] = fmaf(w2, f.z, aR[2]); aR[3] = fmaf(w2, f.w, aR[3]);
            f = shf2[3*j+1];
            aR[4] = fmaf(w2, f.x, aR[4]); aR[5] = fmaf(w2, f.y, aR[5]);
            aR[6] = fmaf(w2, f.z, aR[6]); aR[7] = fmaf(w2, f.w, aR[7]);
            f = shf2[3*j+2];
            aR[8] = fmaf(w2, f.x, aR[8]); aR[9] = fmaf(w2, f.y, aR[9]);
            aR[10] = fmaf(w2, f.z, aR[10]); aR[11] = fmaf(w2, f.w, aR[11]);
        }
    }

    const int o = split * L_TGT + l;
    d_pbestL[o] = bestL; d_pidxL[o] = bidxL;
    d_pbestR[o] = bestR; d_pidxR[o] = bidxR;
    d_pnL[o] = nL;       d_pnR[o] = nR;
#pragma unroll
    for (int k = 0; k < 12; k++) {
        d_paccL[(split * 12 + k) * L_TGT + l] = aL[k];
        d_paccR[(split * 12 + k) * L_TGT + l] = aR[k];
    }
}

/* ------------- pass2: reduce splits, gather, normalize, MLP ------------- */
__global__ void __launch_bounds__(NT)
pass2_kernel(const float* __restrict__ g1_x, const float* __restrict__ g2_x,
             const float* __restrict__ W1, const float* __restrict__ b1,
             const float* __restrict__ W2, const float* __restrict__ b2,
             float* __restrict__ out) {
    __shared__ float sW1[2500], sb1[50], sW2[50];
    for (int i = threadIdx.x; i < 2500; i += NT) sW1[i] = W1[i];
    if (threadIdx.x < 50) { sb1[threadIdx.x] = b1[threadIdx.x]; sW2[threadIdx.x] = W2[threadIdx.x]; }
    __syncthreads();

    const int l = blockIdx.x * NT + threadIdx.x;

    float bestL = 3.4e38f, bestR = 3.4e38f;
    int bidxL = 0, bidxR = 0;
    float nL = EPSC, nR = EPSC;
    float aL[12], aR[12];
#pragma unroll
    for (int k = 0; k < 12; k++) { aL[k] = 0.f; aR[k] = 0.f; }

    for (int s = 0; s < NSPLIT; s++) {
        int o = s * L_TGT + l;
        float b = d_pbestL[o];
        if (b < bestL) { bestL = b; bidxL = d_pidxL[o]; }
        float c = d_pbestR[o];
        if (c < bestR) { bestR = c; bidxR = d_pidxR[o]; }
        nL += d_pnL[o]; nR += d_pnR[o];
#pragma unroll
        for (int k = 0; k < 12; k++) {
            aL[k] += d_paccL[(s * 12 + k) * L_TGT + l];
            aR[k] += d_paccR[(s * 12 + k) * L_TGT + l];
        }
    }

    float x[50];
    const float* gl = &g1_x[bidxL * 12];
    const float* gr = &g2_x[bidxR * 12];
#pragma unroll
    for (int k = 0; k < 12; k++) x[k] = gl[k];
    float invL = 1.f / nL;
#pragma unroll
    for (int k = 0; k < 12; k++) x[12 + k] = aL[k] * invL;
    x[24] = tanhf(nL);
#pragma unroll
    for (int k = 0; k < 12; k++) x[25 + k] = gr[k];
    float invR = 1.f / nR;
#pragma unroll
    for (int k = 0; k < 12; k++) x[37 + k] = aR[k] * invR;
    x[49] = tanhf(nR);

    float outv = b2[0];
    for (int j = 0; j < 50; j++) {
        float h = sb1[j];
#pragma unroll
        for (int i = 0; i < 50; i++) h = fmaf(x[i], sW1[i * 50 + j], h);
        outv = fmaf(fmaxf(h, 0.f), sW2[j], outv);
    }
    out[l] = outv;
}

extern "C" void kernel_launch(void* const* d_in, const int* in_sizes, int n_in,
                              void* d_out, int out_size) {
    const float* locs_left  = (const float*)d_in[0];
    const float* locs_right = (const float*)d_in[1];
    const float* g1_pos     = (const float*)d_in[2];
    const float* g1_x       = (const float*)d_in[3];
    const float* g2_pos     = (const float*)d_in[4];
    const float* g2_x       = (const float*)d_in[5];
    const float* s1_verts   = (const float*)d_in[6];
    const float* s1_x       = (const float*)d_in[7];
    const float* s2_verts   = (const float*)d_in[8];
    const float* s2_x       = (const float*)d_in[9];
    const float* W1         = (const float*)d_in[10];
    const float* b1         = (const float*)d_in[11];
    const float* W2         = (const float*)d_in[12];
    const float* b2         = (const float*)d_in[13];
    float* out = (float*)d_out;

    prep_kernel<<<(N_SRC + NT - 1) / NT, NT>>>(g1_pos, g2_pos, s1_verts, s2_verts);
    dim3 grid1(L_TGT / NT, NSPLIT);
    pass1_kernel<<<grid1, NT>>>(locs_left, locs_right, s1_x, s2_x);
    pass2_kernel<<<L_TGT / NT, NT>>>(g1_x, g2_x, W1, b1, W2, b2, out);
}